// round 2
// baseline (speedup 1.0000x reference)
#include <cuda_runtime.h>

// StructureEncoder: B=524288 elems, 24-joint tree of tiny MLPs (10->10->6).
// Strategy: fma.rn.f32x2 packed FMA over output-feature pairs; weights staged
// in smem with 16B-aligned padded rows so operand pairs load directly as u64
// (zero packing MOVs); per-elem smem slot-reuse buffer (quat staged in ->
// feats overwrite -> coalesced float4 flush); DFS joint order with parent
// features register-passed along chains; E=2 elems/thread sharing all weight
// loads.

#define TILE      256      // batch elements per CTA
#define THREADS   128      // threads per CTA (each handles elems tid, tid+128)
#define ROWSTRIDE 146      // floats per element row in smem buffer (144 + 2 pad)
#define WJ        224      // padded weight floats per joint
#define NJ        24

typedef unsigned long long u64;

__device__ __forceinline__ u64 pk(float a, float b) {
    u64 r; asm("mov.b64 %0,{%1,%2};" : "=l"(r) : "f"(a), "f"(b)); return r;
}
__device__ __forceinline__ void upk(u64 v, float& a, float& b) {
    asm("mov.b64 {%0,%1},%2;" : "=f"(a), "=f"(b) : "l"(v));
}
__device__ __forceinline__ u64 ffma2(u64 a, u64 b, u64 c) {
    u64 d; asm("fma.rn.f32x2 %0,%1,%2,%3;" : "=l"(d) : "l"(a), "l"(b), "l"(c)); return d;
}

// Padded per-joint weight block in smem (base = j*WJ floats, 16B-aligned):
//   [  0..119]  W1 rows r=0..9 (r<4: W1a row r, else W1b row r-4), 12 floats/row
//   [120..131]  b1 (10 + 2 pad)
//   [132..211]  W2 rows k=0..9, 8 floats/row (6 data + 2 pad)
//   [212..219]  b2 (6 + 2 pad)
//   [220..223]  pad
// Row strides 12 and 8 floats keep every row base 16B-aligned, so each pair of
// adjacent output-feature weights reads as one u64 lane-pair with NO mov.

template<int J, int P, bool USE_PREV>
__device__ __forceinline__ void joint_step(const float* __restrict__ wts,
                                           float* __restrict__ bufA, float* __restrict__ bufB,
                                           float (&pfA)[6], float (&pfB)[6])
{
    const int jb = J * WJ;

    // quat for this joint (slots [6J, 6J+4), overwritten by feat below)
    float2 qa0 = *(const float2*)(bufA + 6*J);
    float2 qa1 = *(const float2*)(bufA + 6*J + 2);
    float2 qb0 = *(const float2*)(bufB + 6*J);
    float2 qb1 = *(const float2*)(bufB + 6*J + 2);

    float xA[10], xB[10];
    xA[0]=qa0.x; xA[1]=qa0.y; xA[2]=qa1.x; xA[3]=qa1.y;
    xB[0]=qb0.x; xB[1]=qb0.y; xB[2]=qb1.x; xB[3]=qb1.y;

    if (P >= 0) {
        if (USE_PREV) {
            #pragma unroll
            for (int c = 0; c < 6; c++) { xA[4+c] = pfA[c]; xB[4+c] = pfB[c]; }
        } else {
            float2 pa0=*(const float2*)(bufA+6*P), pa1=*(const float2*)(bufA+6*P+2), pa2=*(const float2*)(bufA+6*P+4);
            float2 pb0=*(const float2*)(bufB+6*P), pb1=*(const float2*)(bufB+6*P+2), pb2=*(const float2*)(bufB+6*P+4);
            xA[4]=pa0.x; xA[5]=pa0.y; xA[6]=pa1.x; xA[7]=pa1.y; xA[8]=pa2.x; xA[9]=pa2.y;
            xB[4]=pb0.x; xB[5]=pb0.y; xB[6]=pb1.x; xB[7]=pb1.y; xB[8]=pb2.x; xB[9]=pb2.y;
        }
    }

    // ---- layer 1: h = relu(x @ W1 + b1), 10 outputs = 5 f32x2 accumulators ----
    ulonglong2 bA = *(const ulonglong2*)(wts + jb + 120);  // b1[0..3]
    ulonglong2 bB = *(const ulonglong2*)(wts + jb + 124);  // b1[4..7]
    u64        bC = *(const u64*)       (wts + jb + 128);  // b1[8..9]
    u64 hA0=bA.x, hA1=bA.y, hA2=bB.x, hA3=bB.y, hA4=bC;
    u64 hB0=bA.x, hB1=bA.y, hB2=bB.x, hB3=bB.y, hB4=bC;

    const int NR = (P >= 0) ? 10 : 4;   // root has no parent features
    #pragma unroll
    for (int r = 0; r < NR; r++) {
        ulonglong2 wAB = *(const ulonglong2*)(wts + jb + r*12);      // W1[r][0..3]
        ulonglong2 wCD = *(const ulonglong2*)(wts + jb + r*12 + 4);  // W1[r][4..7]
        u64        wE  = *(const u64*)       (wts + jb + r*12 + 8);  // W1[r][8..9]
        u64 xa = pk(xA[r], xA[r]);
        hA0 = ffma2(xa, wAB.x, hA0); hA1 = ffma2(xa, wAB.y, hA1);
        hA2 = ffma2(xa, wCD.x, hA2); hA3 = ffma2(xa, wCD.y, hA3);
        hA4 = ffma2(xa, wE,    hA4);
        u64 xb = pk(xB[r], xB[r]);
        hB0 = ffma2(xb, wAB.x, hB0); hB1 = ffma2(xb, wAB.y, hB1);
        hB2 = ffma2(xb, wCD.x, hB2); hB3 = ffma2(xb, wCD.y, hB3);
        hB4 = ffma2(xb, wE,    hB4);
    }

    float sA[10], sB[10];
    {
        float a, b;
        upk(hA0,a,b); sA[0]=fmaxf(a,0.f); sA[1]=fmaxf(b,0.f);
        upk(hA1,a,b); sA[2]=fmaxf(a,0.f); sA[3]=fmaxf(b,0.f);
        upk(hA2,a,b); sA[4]=fmaxf(a,0.f); sA[5]=fmaxf(b,0.f);
        upk(hA3,a,b); sA[6]=fmaxf(a,0.f); sA[7]=fmaxf(b,0.f);
        upk(hA4,a,b); sA[8]=fmaxf(a,0.f); sA[9]=fmaxf(b,0.f);
        upk(hB0,a,b); sB[0]=fmaxf(a,0.f); sB[1]=fmaxf(b,0.f);
        upk(hB1,a,b); sB[2]=fmaxf(a,0.f); sB[3]=fmaxf(b,0.f);
        upk(hB2,a,b); sB[4]=fmaxf(a,0.f); sB[5]=fmaxf(b,0.f);
        upk(hB3,a,b); sB[6]=fmaxf(a,0.f); sB[7]=fmaxf(b,0.f);
        upk(hB4,a,b); sB[8]=fmaxf(a,0.f); sB[9]=fmaxf(b,0.f);
    }

    // ---- layer 2: feat = relu(h @ W2 + b2), 6 outputs = 3 f32x2 accumulators ----
    ulonglong2 c01 = *(const ulonglong2*)(wts + jb + 212);  // b2[0..3]
    u64        c2  = *(const u64*)       (wts + jb + 216);  // b2[4..5]
    u64 fA0=c01.x, fA1=c01.y, fA2=c2;
    u64 fB0=c01.x, fB1=c01.y, fB2=c2;

    #pragma unroll
    for (int k = 0; k < 10; k++) {
        ulonglong2 v01 = *(const ulonglong2*)(wts + jb + 132 + k*8);  // W2[k][0..3]
        u64        v2  = *(const u64*)       (wts + jb + 136 + k*8);  // W2[k][4..5]
        u64 da = pk(sA[k], sA[k]);
        fA0 = ffma2(da, v01.x, fA0); fA1 = ffma2(da, v01.y, fA1); fA2 = ffma2(da, v2, fA2);
        u64 db = pk(sB[k], sB[k]);
        fB0 = ffma2(db, v01.x, fB0); fB1 = ffma2(db, v01.y, fB1); fB2 = ffma2(db, v2, fB2);
    }

    {
        float a, b;
        upk(fA0,a,b); pfA[0]=fmaxf(a,0.f); pfA[1]=fmaxf(b,0.f);
        upk(fA1,a,b); pfA[2]=fmaxf(a,0.f); pfA[3]=fmaxf(b,0.f);
        upk(fA2,a,b); pfA[4]=fmaxf(a,0.f); pfA[5]=fmaxf(b,0.f);
        upk(fB0,a,b); pfB[0]=fmaxf(a,0.f); pfB[1]=fmaxf(b,0.f);
        upk(fB1,a,b); pfB[2]=fmaxf(a,0.f); pfB[3]=fmaxf(b,0.f);
        upk(fB2,a,b); pfB[4]=fmaxf(a,0.f); pfB[5]=fmaxf(b,0.f);
    }

    // feat overwrites this joint's slots [6J, 6J+6)
    *(float2*)(bufA + 6*J)     = make_float2(pfA[0], pfA[1]);
    *(float2*)(bufA + 6*J + 2) = make_float2(pfA[2], pfA[3]);
    *(float2*)(bufA + 6*J + 4) = make_float2(pfA[4], pfA[5]);
    *(float2*)(bufB + 6*J)     = make_float2(pfB[0], pfB[1]);
    *(float2*)(bufB + 6*J + 2) = make_float2(pfB[2], pfB[3]);
    *(float2*)(bufB + 6*J + 4) = make_float2(pfB[4], pfB[5]);
}

__global__ void __launch_bounds__(THREADS, 1)
se_kernel(const float* __restrict__ quat, const float* __restrict__ W1a,
          const float* __restrict__ W1b, const float* __restrict__ b1,
          const float* __restrict__ W2,  const float* __restrict__ b2,
          float* __restrict__ out)
{
    extern __shared__ float smem[];
    float* buf = smem;                         // [TILE][ROWSTRIDE]
    float* wts = smem + TILE * ROWSTRIDE;      // [NJ * WJ]  (16B-aligned: 149504 B offset)
    const int tid = threadIdx.x;

    // ---- stage weights into padded smem layout ----
    for (int i = tid; i < NJ * WJ; i += THREADS) {
        int j = i / WJ, o = i - j * WJ;
        float v = 0.f;
        if (o < 120) {
            int r = o / 12, k = o - r * 12;
            if (k < 10) v = (r < 4) ? W1a[j*40 + r*10 + k] : W1b[j*60 + (r-4)*10 + k];
        } else if (o < 132) {
            int t = o - 120; if (t < 10) v = b1[j*10 + t];
        } else if (o < 212) {
            int t = o - 132; int k = t / 8, c = t - k * 8;
            if (c < 6) v = W2[j*60 + k*6 + c];
        } else if (o < 220) {
            int t = o - 212; if (t < 6) v = b2[j*6 + t];
        }
        wts[i] = v;
    }

    // ---- stage quat coalesced: gmem float4 -> buffer slots [elem][6j..6j+4) ----
    const float4* qsrc = (const float4*)(quat + (size_t)blockIdx.x * TILE * 96);
    #pragma unroll
    for (int w = 0; w < 48; w++) {
        int n = tid + w * THREADS;            // float4 index within tile (< 6144)
        float4 v = qsrc[n];
        int e = n / 24, jj = n - e * 24;      // one float4 == quat of (elem e, joint jj)
        float* dst = buf + e * ROWSTRIDE + jj * 6;
        *(float2*)dst       = make_float2(v.x, v.y);
        *(float2*)(dst + 2) = make_float2(v.z, v.w);
    }
    __syncthreads();

    // ---- DFS over joint tree; parent feature register-passed along chains ----
    float* bufA = buf + tid * ROWSTRIDE;
    float* bufB = buf + (tid + 128) * ROWSTRIDE;
    float pfA[6], pfB[6];

    joint_step< 0, -1, false>(wts, bufA, bufB, pfA, pfB);
    joint_step< 1,  0, true >(wts, bufA, bufB, pfA, pfB);
    joint_step< 4,  1, true >(wts, bufA, bufB, pfA, pfB);
    joint_step< 7,  4, true >(wts, bufA, bufB, pfA, pfB);
    joint_step<10,  7, true >(wts, bufA, bufB, pfA, pfB);
    joint_step< 2,  0, false>(wts, bufA, bufB, pfA, pfB);
    joint_step< 5,  2, true >(wts, bufA, bufB, pfA, pfB);
    joint_step< 8,  5, true >(wts, bufA, bufB, pfA, pfB);
    joint_step<11,  8, true >(wts, bufA, bufB, pfA, pfB);
    joint_step< 3,  0, false>(wts, bufA, bufB, pfA, pfB);
    joint_step< 6,  3, true >(wts, bufA, bufB, pfA, pfB);
    joint_step< 9,  6, true >(wts, bufA, bufB, pfA, pfB);
    joint_step<12,  9, true >(wts, bufA, bufB, pfA, pfB);
    joint_step<15, 12, true >(wts, bufA, bufB, pfA, pfB);
    joint_step<13,  9, false>(wts, bufA, bufB, pfA, pfB);
    joint_step<16, 13, true >(wts, bufA, bufB, pfA, pfB);
    joint_step<18, 16, true >(wts, bufA, bufB, pfA, pfB);
    joint_step<20, 18, true >(wts, bufA, bufB, pfA, pfB);
    joint_step<22, 20, true >(wts, bufA, bufB, pfA, pfB);
    joint_step<14,  9, false>(wts, bufA, bufB, pfA, pfB);
    joint_step<17, 14, true >(wts, bufA, bufB, pfA, pfB);
    joint_step<19, 17, true >(wts, bufA, bufB, pfA, pfB);
    joint_step<21, 19, true >(wts, bufA, bufB, pfA, pfB);
    joint_step<23, 21, true >(wts, bufA, bufB, pfA, pfB);

    __syncthreads();

    // ---- coalesced flush: buffer rows are exactly the 144-float output rows ----
    float* obase = out + (size_t)blockIdx.x * TILE * 144;
    #pragma unroll
    for (int w = 0; w < 72; w++) {
        int m = tid + w * THREADS;            // float4 index (< 9216)
        int o = m * 4;
        int e = o / 144, col = o - e * 144;   // 144 % 4 == 0 -> never crosses rows
        const float* s = buf + e * ROWSTRIDE + col;
        float2 lo = *(const float2*)s;
        float2 hi = *(const float2*)(s + 2);
        *(float4*)(obase + o) = make_float4(lo.x, lo.y, hi.x, hi.y);
    }
}

extern "C" void kernel_launch(void* const* d_in, const int* in_sizes, int n_in,
                              void* d_out, int out_size)
{
    const float* quat = (const float*)d_in[0];
    const float* W1a  = (const float*)d_in[1];
    const float* W1b  = (const float*)d_in[2];
    const float* b1   = (const float*)d_in[3];
    const float* W2   = (const float*)d_in[4];
    const float* b2   = (const float*)d_in[5];
    float* out = (float*)d_out;

    int B = in_sizes[0] / 96;                 // quat = B * 24 * 4 floats
    int blocks = B / TILE;                    // 524288 / 256 = 2048

    size_t smem_bytes = (size_t)(TILE * ROWSTRIDE + NJ * WJ) * sizeof(float); // 171008
    cudaFuncSetAttribute(se_kernel, cudaFuncAttributeMaxDynamicSharedMemorySize,
                         (int)smem_bytes);

    se_kernel<<<blocks, THREADS, smem_bytes>>>(quat, W1a, W1b, b1, W2, b2, out);
}